// round 8
// baseline (speedup 1.0000x reference)
#include <cuda_runtime.h>
#include <cuda_bf16.h>

#define OUT_W    256
#define IMG_W    512
#define NPAIR    128            // one block per ii-pair
#define SK_T     33             // K rows per block
#define SK_E     792            // bf16/row; stride 1584B ≡ 48 mod 128 -> conflict-free
#define SK_W     396            // u32 words per row
#define SREV_LEN 1032
#define OFF_K     0
#define OFF_SREV  52272         // 33*396*4
#define OFF_SREVB 56400         // + 2*1032*2
#define SMEM_BYTES 60528

#define NCHUNK   256            // 2 chunks per ii-pair (s-specialized warps)

__device__ float g_part[NCHUNK * 32 * OUT_W];   // 8 MB partials [chunk][i][j]
__device__ float g_red[16 * 32 * OUT_W];        // 512 KB stage-A output

__device__ __forceinline__ float frcp(float x) {
    float r; asm("rcp.approx.f32 %0, %1;" : "=f"(r) : "f"(x)); return r;
}
__device__ __forceinline__ void mma_bf16(float* d, unsigned a0, unsigned a1,
                                         unsigned a2, unsigned a3,
                                         unsigned b0, unsigned b1) {
    asm volatile(
        "mma.sync.aligned.m16n8k16.row.col.f32.bf16.bf16.f32 "
        "{%0,%1,%2,%3}, {%4,%5,%6,%7}, {%8,%9}, {%0,%1,%2,%3};"
        : "+f"(d[0]), "+f"(d[1]), "+f"(d[2]), "+f"(d[3])
        : "r"(a0), "r"(a1), "r"(a2), "r"(a3), "r"(b0), "r"(b1));
}

// ---------------------------------------------------------------------------
// Block p: ii in {2p, 2p+1}. 256 threads, 8 warps = (4 j-strips) x (2 s).
// Warp (wj, s): j in [64wj, 64wj+64) [4 m-tiles], i in [0,32) [4 n-tiles],
// k = e in [64wj, 64wj+576), single image row s. 16 MMAs per k-step share
// one B fetch; A is the Toeplitz image window (2 fresh LDS + 7 shifts/step).
// ---------------------------------------------------------------------------
__global__ void __launch_bounds__(256, 1)
conv_mma_kernel(const float* __restrict__ img, const float* __restrict__ pos) {
    extern __shared__ char smem[];
    unsigned*      skw = (unsigned*)(smem + OFF_K);
    __nv_bfloat16* sr  = (__nv_bfloat16*)(smem + OFF_SREV);   // [2][1032]
    __nv_bfloat16* srB = (__nv_bfloat16*)(smem + OFF_SREVB);  // shifted +1

    const int p   = blockIdx.x;
    const int tid = threadIdx.x;
    const float p0 = pos[0], p1 = pos[1];

    // ---- reversed image rows (bf16): sr[s][z] = img[2p+s][767-z], z in [256,767]
    for (int x = tid; x < 2 * SREV_LEN; x += 256) {
        int s = (x >= SREV_LEN) ? 1 : 0;
        int z = x - s * SREV_LEN;
        float v0 = (z >= 256 && z <= 767) ? img[(2 * p + s) * IMG_W + (767 - z)] : 0.f;
        int z1 = z + 1;
        float v1 = (z1 >= 256 && z1 <= 767) ? img[(2 * p + s) * IMG_W + (767 - z1)] : 0.f;
        sr [x] = __float2bfloat16_rn(v0);
        srB[x] = __float2bfloat16_rn(v1);
    }
    // ---- K rows: row t holds d-255 = t - 1 - 2p ; zero for e >= 767
    for (int t = 0; t < SK_T; t++) {
        float dx  = (float)(t - 1 - 2 * p) + p0;
        float dx2 = dx * dx;
        for (int u = tid; u < SK_W; u += 256) {
            float dy0 = (float)(2 * u - 511) + p1;
            float dy1 = dy0 + 1.0f;
            float v0 = (2 * u     < 767) ? frcp(fmaf(dy0, dy0, dx2)) : 0.f;
            float v1 = (2 * u + 1 < 767) ? frcp(fmaf(dy1, dy1, dx2)) : 0.f;
            unsigned wv;
            asm("cvt.rn.bf16x2.f32 %0, %1, %2;" : "=r"(wv) : "f"(v1), "f"(v0));
            skw[t * SK_W + u] = wv;
        }
    }
    __syncthreads();

    const int w    = tid >> 5;
    const int s    = w >> 2;          // image row within pair
    const int wj   = w & 3;           // j strip [64wj, 64wj+64)
    const int lane = tid & 31;
    const int r    = lane >> 2;
    const int c    = lane & 3;
    const int sel  = r & 1;

    const unsigned* As = (const unsigned*)(sel ? (srB + s * SREV_LEN)
                                               : (sr  + s * SREV_LEN));
    const int aw0 = (2 * c - 64 * wj - r + 256 - sel) >> 1;
    const unsigned* pB = skw + (r + 1 - s) * SK_W + c;

    float acc[4][4][4];
#pragma unroll
    for (int m = 0; m < 4; m++)
#pragma unroll
        for (int n = 0; n < 4; n++)
#pragma unroll
            for (int k = 0; k < 4; k++) acc[m][n][k] = 0.f;

    // A window: A_[k] = As[aw0 + ew + 4 - 4k], k=0..8  (m-tile m: a2=A[2m],
    // a0=a3=A[2m+1], a1=A[2m+2]).  Slide: A(q+1)[k] = A(q)[k-2].
#define LOADA_FULL(A_, ew_)                                                   \
    { _Pragma("unroll")                                                       \
      for (int k = 0; k < 9; k++) A_[k] = As[aw0 + (ew_) + 4 - 4 * k]; }
#define LOADA_SLIDE(D_, S_, ew_)                                              \
    { _Pragma("unroll")                                                       \
      for (int k = 8; k >= 2; k--) D_[k] = S_[k - 2];                         \
      D_[1] = As[aw0 + (ew_)];                                                \
      D_[0] = As[aw0 + (ew_) + 4]; }
#define LOADB(B_, ew_)                                                        \
    { _Pragma("unroll")                                                       \
      for (int nn = 0; nn < 4; nn++) {                                        \
          B_[2 * nn]     = pB[8 * nn * SK_W + (ew_)];                         \
          B_[2 * nn + 1] = pB[8 * nn * SK_W + (ew_) + 4];                     \
      } }
#define MMAQ(A_, B_)                                                          \
    { _Pragma("unroll")                                                       \
      for (int m = 0; m < 4; m++)                                             \
          _Pragma("unroll")                                                   \
          for (int n = 0; n < 4; n++)                                         \
              mma_bf16(acc[m][n], A_[2*m+1], A_[2*m+2], A_[2*m], A_[2*m+1],   \
                       B_[2*n], B_[2*n+1]); }

    unsigned aX[9], bX[8], aY[9], bY[8];
    int ew = 32 * wj;
    LOADA_FULL(aX, ew); LOADB(bX, ew);
#pragma unroll 1
    for (int it = 0; it < 17; it++) {
        LOADA_SLIDE(aY, aX, ew + 8); LOADB(bY, ew + 8);
        MMAQ(aX, bX);
        LOADA_SLIDE(aX, aY, ew + 16); LOADB(bX, ew + 16);
        MMAQ(aY, bY);
        ew += 16;
    }
    LOADA_SLIDE(aY, aX, ew + 8); LOADB(bY, ew + 8);
    MMAQ(aX, bX);
    MMAQ(aY, bY);
#undef LOADA_FULL
#undef LOADA_SLIDE
#undef LOADB
#undef MMAQ

    // ---- partials: chunk = 2p + s ; D rows = j, cols = i
    float* dst = g_part + (2 * p + s) * (32 * OUT_W);
#pragma unroll
    for (int m = 0; m < 4; m++) {
        const int j0 = 64 * wj + 16 * m + r;
#pragma unroll
        for (int n = 0; n < 4; n++) {
            const int i0 = 8 * n + 2 * c;
            dst[(i0    ) * OUT_W + j0    ] = acc[m][n][0];
            dst[(i0 + 1) * OUT_W + j0    ] = acc[m][n][1];
            dst[(i0    ) * OUT_W + j0 + 8] = acc[m][n][2];
            dst[(i0 + 1) * OUT_W + j0 + 8] = acc[m][n][3];
        }
    }
}

// ---------------------------------------------------------------------------
// Two-stage deterministic reduction over 256 chunks.
// ---------------------------------------------------------------------------
__global__ void reduce_a_kernel() {
    const int g  = blockIdx.x >> 5;                  // 16 groups of 16 chunks
    const int o  = (blockIdx.x & 31) * 256 + threadIdx.x;
    const int c0 = g * 16;
    float s0 = 0.f, s1 = 0.f, s2 = 0.f, s3 = 0.f;
#pragma unroll
    for (int c = 0; c < 16; c += 4) {
        s0 += g_part[(c0 + c + 0) * 8192 + o];
        s1 += g_part[(c0 + c + 1) * 8192 + o];
        s2 += g_part[(c0 + c + 2) * 8192 + o];
        s3 += g_part[(c0 + c + 3) * 8192 + o];
    }
    g_red[g * 8192 + o] = (s0 + s1) + (s2 + s3);
}

__global__ void reduce_b_kernel(float* __restrict__ out) {
    const int o = blockIdx.x * 256 + threadIdx.x;
    float s = 0.f;
#pragma unroll
    for (int g = 0; g < 16; g++) s += g_red[g * 8192 + o];
    out[o] = s;
}

// ---------------------------------------------------------------------------
extern "C" void kernel_launch(void* const* d_in, const int* in_sizes, int n_in,
                              void* d_out, int out_size) {
    const float* img = (const float*)d_in[0];   // [256, 512] f32
    const float* pos = (const float*)d_in[1];   // [2] f32
    float* out = (float*)d_out;                 // [32, 256] f32

    cudaFuncSetAttribute(conv_mma_kernel,
                         cudaFuncAttributeMaxDynamicSharedMemorySize, SMEM_BYTES);
    conv_mma_kernel<<<NPAIR, 256, SMEM_BYTES>>>(img, pos);
    reduce_a_kernel<<<512, 256>>>();
    reduce_b_kernel<<<32, 256>>>(out);
}

// round 9
// speedup vs baseline: 1.0065x; 1.0065x over previous
#include <cuda_runtime.h>
#include <cuda_bf16.h>

#define OUT_W    256
#define IMG_W    512
#define NBLK     512            // (ii in 256) x (i-half h in 2)
#define SK_T     16             // K rows per block (i-span 16, single ii)
#define SK_W     388            // u32 (bf16x2) words per K row; 1552B = 16 mod 128
#define SREV_LEN 1032
#define OFF_K     0
#define OFF_SREV  24832         // 16*388*4
#define OFF_SREVB 26896         // + 1032*2
#define SMEM_BYTES 28960        // + 1032*2

__device__ float g_part[256 * 2 * 16 * OUT_W];  // 8 MB: [ii][h][16][256]
__device__ float g_red[16 * 32 * OUT_W];        // 512 KB stage-A

__device__ __forceinline__ float frcp(float x) {
    float r; asm("rcp.approx.f32 %0, %1;" : "=f"(r) : "f"(x)); return r;
}
__device__ __forceinline__ void mma_bf16(float* d, unsigned a0, unsigned a1,
                                         unsigned a2, unsigned a3,
                                         unsigned b0, unsigned b1) {
    asm volatile(
        "mma.sync.aligned.m16n8k16.row.col.f32.bf16.bf16.f32 "
        "{%0,%1,%2,%3}, {%4,%5,%6,%7}, {%8,%9}, {%0,%1,%2,%3};"
        : "+f"(d[0]), "+f"(d[1]), "+f"(d[2]), "+f"(d[3])
        : "r"(a0), "r"(a1), "r"(a2), "r"(a3), "r"(b0), "r"(b1));
}

// ---------------------------------------------------------------------------
// Block (ii, h): one image row ii, i in [16h, 16h+16), all j. 8 warps, warp w:
// j in [32w, 32w+32) (2 m-tiles) x 2 n-tiles, k = e in [32w, 32w+544).
// GEMM M=j N=i K=e, bf16 m16n8k16; A = Toeplitz reversed-image window read in
// place (5 LDS/step via cross-m word sharing, a3==a0); B = 16 K rows built
// in-SMEM (cheap: ~0.4K MUFU warp-instr/block). 512 blocks = 1 full wave,
// 4 blocks/SM resident -> 8 warps/SMSP hide LDS->MMA latency.
// ---------------------------------------------------------------------------
__global__ void __launch_bounds__(256, 4)
conv_mma_kernel(const float* __restrict__ img, const float* __restrict__ pos) {
    extern __shared__ char smem[];
    unsigned*      skw = (unsigned*)(smem + OFF_K);
    __nv_bfloat16* sr  = (__nv_bfloat16*)(smem + OFF_SREV);   // reversed row
    __nv_bfloat16* srB = (__nv_bfloat16*)(smem + OFF_SREVB);  // shifted +1

    const int ii  = blockIdx.x >> 1;
    const int h   = blockIdx.x & 1;
    const int tid = threadIdx.x;
    const float p0 = pos[0], p1 = pos[1];

    // ---- stage reversed image row (bf16): sr[z] = img[ii][767-z], z in [256,767]
    for (int z = tid; z < SREV_LEN; z += 256) {
        float v0 = (z >= 256 && z <= 767) ? img[ii * IMG_W + (767 - z)] : 0.f;
        int z1 = z + 1;
        float v1 = (z1 >= 256 && z1 <= 767) ? img[ii * IMG_W + (767 - z1)] : 0.f;
        sr [z] = __float2bfloat16_rn(v0);
        srB[z] = __float2bfloat16_rn(v1);
    }
    // ---- K rows: row t serves i = 16h + t  (d-255 = 16h + t - ii)
    for (int t = 0; t < SK_T; t++) {
        float dx  = (float)(16 * h + t - ii) + p0;
        float dx2 = dx * dx;
        for (int u = tid; u < SK_W; u += 256) {
            float dy0 = (float)(2 * u - 511) + p1;
            float dy1 = dy0 + 1.0f;
            float v0 = (2 * u     < 767) ? frcp(fmaf(dy0, dy0, dx2)) : 0.f;
            float v1 = (2 * u + 1 < 767) ? frcp(fmaf(dy1, dy1, dx2)) : 0.f;
            unsigned wv;
            asm("cvt.rn.bf16x2.f32 %0, %1, %2;" : "=r"(wv) : "f"(v1), "f"(v0));
            skw[t * SK_W + u] = wv;
        }
    }
    __syncthreads();

    const int w    = tid >> 5;        // j strip [32w, 32w+32)
    const int lane = tid & 31;
    const int r    = lane >> 2;
    const int c    = lane & 3;
    const int sel  = r & 1;

    const unsigned* As = (const unsigned*)(sel ? srB : sr);
    const int aw0 = (2 * c - 32 * w - r + 256 - sel) >> 1;
    const unsigned* pB = skw + r * SK_W + c;       // n-tile nn: + 8*nn*SK_W

    float acc[2][2][4];
#pragma unroll
    for (int m = 0; m < 2; m++)
#pragma unroll
        for (int n = 0; n < 2; n++)
#pragma unroll
            for (int k = 0; k < 4; k++) acc[m][n][k] = 0.f;

#pragma unroll 1
    for (int q = 0; q < 34; q++) {
        const int ew = 16 * w + 8 * q;             // e-word offset
        const int w0 = aw0 + ew;
        // A window, shared across m-tiles: W[k] = As[w0 + 4 - 4k]
        unsigned W0 = As[w0 + 4], W1 = As[w0], W2 = As[w0 - 4],
                 W3 = As[w0 - 8], W4 = As[w0 - 12];
        unsigned b00 = pB[ew],            b01 = pB[ew + 4];
        unsigned b10 = pB[8 * SK_W + ew], b11 = pB[8 * SK_W + ew + 4];
        // m=0: a0=W1 a1=W2 a2=W0 a3=W1 ; m=1: a0=W3 a1=W4 a2=W2 a3=W3
        mma_bf16(acc[0][0], W1, W2, W0, W1, b00, b01);
        mma_bf16(acc[0][1], W1, W2, W0, W1, b10, b11);
        mma_bf16(acc[1][0], W3, W4, W2, W3, b00, b01);
        mma_bf16(acc[1][1], W3, W4, W2, W3, b10, b11);
    }

    // ---- partials: chunk (ii, h), local rows il = 8nn + 2c, cols j
    float* dst = g_part + (ii * 2 + h) * (16 * OUT_W);
#pragma unroll
    for (int m = 0; m < 2; m++) {
        const int j0 = 32 * w + 16 * m + r;
#pragma unroll
        for (int nn = 0; nn < 2; nn++) {
            const int il = 8 * nn + 2 * c;
            dst[(il    ) * OUT_W + j0    ] = acc[m][nn][0];
            dst[(il + 1) * OUT_W + j0    ] = acc[m][nn][1];
            dst[(il    ) * OUT_W + j0 + 8] = acc[m][nn][2];
            dst[(il + 1) * OUT_W + j0 + 8] = acc[m][nn][3];
        }
    }
}

// ---------------------------------------------------------------------------
// Reduction over 256 ii-chunks (stride 8192 floats), float4-vectorized,
// deterministic order. g_part[ii*8192 + o8] with o8 = i*256 + j.
// ---------------------------------------------------------------------------
__global__ void reduce_a_kernel() {
    const float4* src = (const float4*)g_part;
    float4*       dstv = (float4*)g_red;
    const int g    = blockIdx.x >> 3;                 // 16 groups of 16 ii
    const int idx4 = (blockIdx.x & 7) * 256 + threadIdx.x;   // [0, 2048)
    float4 s = make_float4(0.f, 0.f, 0.f, 0.f);
#pragma unroll 4
    for (int t = 0; t < 16; t++) {
        float4 v = src[(16 * g + t) * 2048 + idx4];
        s.x += v.x; s.y += v.y; s.z += v.z; s.w += v.w;
    }
    dstv[g * 2048 + idx4] = s;
}

__global__ void reduce_b_kernel(float* __restrict__ out) {
    const float4* src = (const float4*)g_red;
    const int idx4 = blockIdx.x * 256 + threadIdx.x;  // [0, 2048)
    float4 s = make_float4(0.f, 0.f, 0.f, 0.f);
#pragma unroll
    for (int g = 0; g < 16; g++) {
        float4 v = src[g * 2048 + idx4];
        s.x += v.x; s.y += v.y; s.z += v.z; s.w += v.w;
    }
    ((float4*)out)[idx4] = s;
}

// ---------------------------------------------------------------------------
extern "C" void kernel_launch(void* const* d_in, const int* in_sizes, int n_in,
                              void* d_out, int out_size) {
    const float* img = (const float*)d_in[0];   // [256, 512] f32
    const float* pos = (const float*)d_in[1];   // [2] f32
    float* out = (float*)d_out;                 // [32, 256] f32

    conv_mma_kernel<<<NBLK, 256, SMEM_BYTES>>>(img, pos);
    reduce_a_kernel<<<128, 256>>>();
    reduce_b_kernel<<<8, 256>>>(out);
}